// round 1
// baseline (speedup 1.0000x reference)
#include <cuda_runtime.h>

#define NUM_SKILLS 300
#define EMB 256
#define CD 64
#define BB 512
#define SS 200

// Scratch (no allocations allowed): per-(b,s) scalars and per-e coefficients.
// g_scal[bs] = {q_f, attempts_f, mastery, valid_f}
__device__ float4 g_scal[BB * SS];
__device__ float  g_A[EMB];
__device__ float  g_B[EMB];
__device__ float  g_C[EMB];
__device__ float  g_D[EMB];

// ---------------------------------------------------------------------------
// Kernel 1: blocks 0..BB-1 compute running counts for one batch row each via
// the O(S^2) triangular formulation (S=200 -> trivial). Block BB computes the
// collapsed einsum coefficients A,B,C,D (256 threads, one e each).
// ---------------------------------------------------------------------------
__global__ void __launch_bounds__(256) prep_kernel(
    const int* __restrict__ q, const int* __restrict__ r,
    const float* __restrict__ skill_w, const float* __restrict__ skill_b,
    const float* __restrict__ att_w,   const float* __restrict__ att_b,
    const float* __restrict__ mast_w,  const float* __restrict__ mast_b,
    const float* __restrict__ proj_w,  const float* __restrict__ proj_b)
{
    const int blk = blockIdx.x;
    if (blk < BB) {
        __shared__ int           qs[SS];   // clipped skill index
        __shared__ unsigned char vs[SS];   // valid flag
        __shared__ unsigned char rs[SS];   // response (0/1)
        const int t = threadIdx.x;
        int qraw = 0;
        if (t < SS) {
            qraw = q[blk * SS + t];
            const bool v = (qraw >= 0) && (qraw < NUM_SKILLS);
            int qc = qraw < 0 ? 0 : (qraw > NUM_SKILLS - 1 ? NUM_SKILLS - 1 : qraw);
            qs[t] = qc;
            vs[t] = v ? 1 : 0;
            rs[t] = (unsigned char)r[blk * SS + t];
        }
        __syncthreads();
        if (t < SS) {
            const int myq = qs[t];
            int att = 0, cor = 0;
            for (int tp = 0; tp <= t; ++tp) {
                const int m = (qs[tp] == myq) & (int)vs[tp];
                att += m;
                cor += m & (int)rs[tp];
            }
            const float attf   = (float)att;
            const float mast   = (float)cor / fmaxf(attf, 1.0f);
            const float qf     = (float)qraw;
            const float validf = vs[t] ? 1.0f : 0.0f;
            g_scal[blk * SS + t] = make_float4(qf, attf, mast, validf);
        }
    } else {
        // Coefficient block: out[b,s,e] = qf*A[e] + att*B[e] + mast*C[e] + D[e]
        //   A[e] = sum_{c<21}  skill_w[c] * proj_w[e,c]
        //   B[e] = sum_{c<21}  att_w[c]   * proj_w[e,21+c]
        //   C[e] = sum_{c<22}  mast_w[c]  * proj_w[e,42+c]
        //   D[e] = proj_b[e] + corresponding bias dot-products
        const int e = threadIdx.x;           // 0..255
        const float* pw = proj_w + e * CD;   // row e of [EMB, CD]
        float A = 0.f, Bv = 0.f, Cv = 0.f, D = proj_b[e];
        #pragma unroll
        for (int c = 0; c < 21; ++c) {
            const float p = pw[c];
            A = fmaf(skill_w[c], p, A);
            D = fmaf(skill_b[c], p, D);
        }
        #pragma unroll
        for (int c = 0; c < 21; ++c) {
            const float p = pw[21 + c];
            Bv = fmaf(att_w[c], p, Bv);
            D  = fmaf(att_b[c], p, D);
        }
        #pragma unroll
        for (int c = 0; c < 22; ++c) {
            const float p = pw[42 + c];
            Cv = fmaf(mast_w[c], p, Cv);
            D  = fmaf(mast_b[c], p, D);
        }
        g_A[e] = A; g_B[e] = Bv; g_C[e] = Cv; g_D[e] = D;
    }
}

// ---------------------------------------------------------------------------
// Kernel 2: pure store-bandwidth kernel. One float4 of the output per thread.
// Total float4s = 512*200*256/4 = 6,553,600 -> 25600 blocks x 256 threads
// (exact, no bounds checks). Coefficients hit L1; scalars broadcast across
// the 16 consecutive threads (64 float4s per (b,s)) sharing one cacheline.
// ---------------------------------------------------------------------------
__global__ void __launch_bounds__(256) out_kernel(float* __restrict__ out)
{
    const int idx = blockIdx.x * blockDim.x + threadIdx.x;  // float4 index
    const int e4  = idx & 63;       // which float4 within the 256-wide e dim
    const int bs  = idx >> 6;       // which (b,s)

    const float4 s = g_scal[bs];
    const float4 a = reinterpret_cast<const float4*>(g_A)[e4];
    const float4 b = reinterpret_cast<const float4*>(g_B)[e4];
    const float4 c = reinterpret_cast<const float4*>(g_C)[e4];
    const float4 d = reinterpret_cast<const float4*>(g_D)[e4];

    float4 o;
    if (s.w != 0.0f) {
        o.x = fmaf(s.x, a.x, fmaf(s.y, b.x, fmaf(s.z, c.x, d.x)));
        o.y = fmaf(s.x, a.y, fmaf(s.y, b.y, fmaf(s.z, c.y, d.y)));
        o.z = fmaf(s.x, a.z, fmaf(s.y, b.z, fmaf(s.z, c.z, d.z)));
        o.w = fmaf(s.x, a.w, fmaf(s.y, b.w, fmaf(s.z, c.w, d.w)));
    } else {
        o = make_float4(0.f, 0.f, 0.f, 0.f);
    }
    reinterpret_cast<float4*>(out)[idx] = o;
}

// ---------------------------------------------------------------------------
// Input order (metadata): 0=q 1=r 2=qry(unused) 3=skill_w 4=skill_b
// 5=att_w 6=att_b 7=mast_w 8=mast_b 9=proj_w 10=proj_b
// ---------------------------------------------------------------------------
extern "C" void kernel_launch(void* const* d_in, const int* in_sizes, int n_in,
                              void* d_out, int out_size)
{
    const int*   q       = (const int*)d_in[0];
    const int*   r       = (const int*)d_in[1];
    const float* skill_w = (const float*)d_in[3];
    const float* skill_b = (const float*)d_in[4];
    const float* att_w   = (const float*)d_in[5];
    const float* att_b   = (const float*)d_in[6];
    const float* mast_w  = (const float*)d_in[7];
    const float* mast_b  = (const float*)d_in[8];
    const float* proj_w  = (const float*)d_in[9];
    const float* proj_b  = (const float*)d_in[10];
    float* out = (float*)d_out;

    prep_kernel<<<BB + 1, 256>>>(q, r, skill_w, skill_b, att_w, att_b,
                                 mast_w, mast_b, proj_w, proj_b);

    const int total4 = BB * SS * EMB / 4;   // 6,553,600
    out_kernel<<<total4 / 256, 256>>>(out);
}